// round 3
// baseline (speedup 1.0000x reference)
#include <cuda_runtime.h>
#include <cstdint>

#define EPS_BN 1e-5f
typedef unsigned long long u64;

// ---------------- folded / repacked parameters ----------------
// d_wd layout: [(kq*2 + kp)*16 + c] = packed f32x2 (Wf[c][kq*4+kp*2], Wf[c][kq*4+kp*2+1])
__device__ u64   d_wd[6144];
__device__ float d_t1[16];
__device__ float d_W2f[64];
__device__ float d_t2[4];
__device__ float d_w3v[4];
__device__ float d_b3v;

__device__ __forceinline__ u64 pack2(float a, float b) {
    return ((u64)__float_as_uint(b) << 32) | (u64)__float_as_uint(a);
}

__global__ void prep_kernel(const float* __restrict__ w1, const float* __restrict__ b1,
                            const float* __restrict__ g1, const float* __restrict__ be1,
                            const float* __restrict__ m1, const float* __restrict__ v1,
                            const float* __restrict__ w2, const float* __restrict__ b2,
                            const float* __restrict__ g2, const float* __restrict__ be2,
                            const float* __restrict__ m2, const float* __restrict__ v2,
                            const float* __restrict__ w3, const float* __restrict__ b3) {
    int t = blockIdx.x * 256 + threadIdx.x;
    if (t < 6144) {
        int c  = t & 15;
        int kp = (t >> 4) & 1;
        int kq = t >> 5;
        int k  = kq * 4 + kp * 2;
        float s1 = g1[c] * rsqrtf(v1[c] + EPS_BN);
        d_wd[t] = pack2(w1[c * 768 + k] * s1, w1[c * 768 + k + 1] * s1);
    }
    if (t < 16) {
        float s1 = g1[t] * rsqrtf(v1[t] + EPS_BN);
        d_t1[t] = b1[t] * s1 + be1[t] - m1[t] * s1;
    }
    if (t < 64) {
        int o = t >> 4;
        float s2 = g2[o] * rsqrtf(v2[o] + EPS_BN);
        d_W2f[t] = w2[t] * s2;
    }
    if (t < 4) {
        float s2 = g2[t] * rsqrtf(v2[t] + EPS_BN);
        d_t2[t] = b2[t] * s2 + be2[t] - m2[t] * s2;
        d_w3v[t] = w3[t];
    }
    if (t == 0) d_b3v = b3[0];
}

// ---------------- packed f32x2 + cp.async helpers ----------------
__device__ __forceinline__ void ffma2(u64& a, u64 x, u64 w) {
    asm("fma.rn.f32x2 %0, %1, %2, %0;" : "+l"(a) : "l"(x), "l"(w));
}
__device__ __forceinline__ u64 add2(u64 a, u64 b) {
    u64 r;
    asm("add.rn.f32x2 %0, %1, %2;" : "=l"(r) : "l"(a), "l"(b));
    return r;
}
__device__ __forceinline__ float hsum2(u64 a) {
    unsigned lo, hi;
    asm("mov.b64 {%0,%1}, %2;" : "=r"(lo), "=r"(hi) : "l"(a));
    return __uint_as_float(lo) + __uint_as_float(hi);
}
__device__ __forceinline__ void cp16(void* dst, const void* src) {
    unsigned d = (unsigned)__cvta_generic_to_shared(dst);
    asm volatile("cp.async.cg.shared.global [%0], [%1], 16;" :: "r"(d), "l"(src) : "memory");
}
__device__ __forceinline__ void cp_commit() {
    asm volatile("cp.async.commit_group;" ::: "memory");
}
__device__ __forceinline__ void cp_wait1() {
    asm volatile("cp.async.wait_group 1;" ::: "memory");
}

static constexpr int NSM = 148;

// Prefetch one k-chunk (384 of 768 k) of strip s into xb.
// gmem float4 (row rgg, cols 4c..4c+3) == x cell (kq = rg*4 + dxq, patch p): transpose is free.
__device__ __forceinline__ void prefetch_chunk(float4* xb, const float* __restrict__ in,
                                               int s, int cn, int t) {
    const float* gin = in + (size_t)(s >> 5) * 786432 + (size_t)(s & 31) * 8192;
#pragma unroll
    for (int it = 0; it < 12; it++) {
        int idx  = it * 256 + t;      // 0..3071
        int rg   = idx >> 7;          // 0..23
        int col4 = idx & 127;
        int rgg  = cn * 24 + rg;      // global (ch,dy) row
        const float* src = gin + (size_t)(rgg >> 4) * 262144 + (rgg & 15) * 512 + col4 * 4;
        int p = col4 >> 2, dxq = col4 & 3;
        cp16(xb + (rg * 4 + dxq) * 32 + p, src);
    }
}

// SMEM map (bytes):
//   [0,       49152)  wsm   : 6144 u64 weights
//   [49152,  147456)  xbuf  : 2 x 3072 float4 (double-buffered x chunks)
//   [147456, 181248)  part  : 4224 u64 (8 warps x 16 ch x 33-pitch) reduce scratch
//   [181248, 183296)  r1    : 512 floats
//   [183296, 183424)  res   : 32 floats
static constexpr int SMEM_BYTES = 183424;

__global__ void __launch_bounds__(256, 1)
cnn_kernel(const float* __restrict__ in, float* __restrict__ out) {
    extern __shared__ char smem[];
    u64*    wsm  = (u64*)smem;
    float4* xbuf = (float4*)(smem + 49152);
    u64*    part = (u64*)(smem + 147456);
    float*  r1   = (float*)(smem + 181248);
    float*  res  = (float*)(smem + 183296);

    const int t  = threadIdx.x;
    const int pg = t & 7;
    const int cg = (t >> 3) & 1;
    const int kc = t >> 4;          // 0..15 (k split)

    // ---- one-time weight load into SMEM ----
    {
        const float4* src = (const float4*)d_wd;
        float4* dst = (float4*)wsm;
#pragma unroll
        for (int i = 0; i < 12; i++) {
            int u = i * 256 + t;
            cp16(dst + u, src + u);
        }
        cp_commit();
    }

    const int s0 = blockIdx.x;
    int ns = 0;
    for (int s = s0; s < 1024; s += NSM) ns++;
    const int nchunks = ns * 2;

    prefetch_chunk(xbuf,        in, s0, 0, t);
    cp_commit();
    prefetch_chunk(xbuf + 3072, in, s0, 1, t);
    cp_commit();

    u64 acc[8][4];
#pragma unroll
    for (int c = 0; c < 8; c++)
#pragma unroll
        for (int pi = 0; pi < 4; pi++) acc[c][pi] = 0ull;

    for (int j = 0; j < nchunks; j++) {
        cp_wait1();
        __syncthreads();

        const int cn = j & 1;
        const ulonglong2* xb = (const ulonglong2*)(xbuf + cn * 3072);

        // ---- compute: 6 kq iterations, 64 ffma2 each ----
#pragma unroll
        for (int i = 0; i < 6; i++) {
            int kql = i * 16 + kc;
            ulonglong2 xv[4];
#pragma unroll
            for (int pi = 0; pi < 4; pi++)
                xv[pi] = xb[kql * 32 + pi * 8 + pg];

            const ulonglong2* w0p = (const ulonglong2*)(wsm + (cn * 96 + kql) * 32 + cg * 8);
            const ulonglong2* w1p = w0p + 8;   // +16 u64 (kp=1 half)
            u64 wa[8], wb[8];
#pragma unroll
            for (int g = 0; g < 4; g++) {
                ulonglong2 a = w0p[g]; wa[2 * g] = a.x; wa[2 * g + 1] = a.y;
                ulonglong2 b = w1p[g]; wb[2 * g] = b.x; wb[2 * g + 1] = b.y;
            }
#pragma unroll
            for (int c = 0; c < 8; c++)
#pragma unroll
                for (int pi = 0; pi < 4; pi++) {
                    ffma2(acc[c][pi], xv[pi].x, wa[c]);
                    ffma2(acc[c][pi], xv[pi].y, wb[c]);
                }
        }
        __syncthreads();   // everyone done reading buf[cn]

        // ---- prefetch chunk j+2 into the buffer just freed ----
        if (j + 2 < nchunks) {
            int sn = s0 + ((j + 2) >> 1) * NSM;
            prefetch_chunk(xbuf + cn * 3072, in, sn, cn, t);
        }
        cp_commit();       // empty group if nothing issued (keeps counting uniform)

        // ---- strip complete: reduce + epilogue + store (overlaps prefetch) ----
        if (cn == 1) {
            const int s = s0 + (j >> 1) * NSM;

            // fold kc parity in-warp (lane bit 4)
#pragma unroll
            for (int c = 0; c < 8; c++)
#pragma unroll
                for (int pi = 0; pi < 4; pi++) {
                    u64 o = __shfl_xor_sync(0xffffffffu, acc[c][pi], 16);
                    acc[c][pi] = add2(acc[c][pi], o);
                }
            if (!(t & 16)) {
                int w = t >> 5;   // == kc>>1
#pragma unroll
                for (int c = 0; c < 8; c++)
#pragma unroll
                    for (int pi = 0; pi < 4; pi++)
                        part[(w * 16 + cg * 8 + c) * 33 + pi * 8 + pg] = acc[c][pi];
            }
            __syncthreads();

            // sum 8 warp-partials per (patch, channel), BN bias + ReLU
#pragma unroll
            for (int jj = 0; jj < 2; jj++) {
                int o = t * 2 + jj;
                int chn = o & 15, p = o >> 4;
                u64 sm_ = part[chn * 33 + p];
#pragma unroll
                for (int w = 1; w < 8; w++) sm_ = add2(sm_, part[(w * 16 + chn) * 33 + p]);
                float v = hsum2(sm_) + d_t1[chn];
                r1[p * 16 + chn] = fmaxf(v, 0.0f);
            }
            __syncthreads();

            // 16->4->1 funnel
            if (t < 32) {
                float z0 = d_t2[0], z1 = d_t2[1], z2 = d_t2[2], z3 = d_t2[3];
#pragma unroll
                for (int c = 0; c < 16; c++) {
                    float r = r1[t * 16 + c];
                    z0 = fmaf(r, d_W2f[c],      z0);
                    z1 = fmaf(r, d_W2f[16 + c], z1);
                    z2 = fmaf(r, d_W2f[32 + c], z2);
                    z3 = fmaf(r, d_W2f[48 + c], z3);
                }
                float o = d_b3v;
                o = fmaf(fmaxf(z0, 0.f), d_w3v[0], o);
                o = fmaf(fmaxf(z1, 0.f), d_w3v[1], o);
                o = fmaf(fmaxf(z2, 0.f), d_w3v[2], o);
                o = fmaf(fmaxf(z3, 0.f), d_w3v[3], o);
                res[t] = o;
            }
            __syncthreads();

            // 16x upsample store: 16 rows x 512 cols, streaming float4
            float* gout = out + (size_t)(s >> 5) * 262144 + (size_t)(s & 31) * 8192;
#pragma unroll
            for (int it = 0; it < 8; it++) {
                int idx  = it * 256 + t;
                int row  = idx >> 7;
                int col4 = idx & 127;
                float v = res[col4 >> 2];
                __stcs((float4*)(gout + row * 512 + col4 * 4), make_float4(v, v, v, v));
            }

#pragma unroll
            for (int c = 0; c < 8; c++)
#pragma unroll
                for (int pi = 0; pi < 4; pi++) acc[c][pi] = 0ull;
        }
    }
}

extern "C" void kernel_launch(void* const* d_in, const int* in_sizes, int n_in,
                              void* d_out, int out_size) {
    (void)in_sizes; (void)n_in; (void)out_size;
    const float* in = (const float*)d_in[0];

    prep_kernel<<<24, 256>>>(
        (const float*)d_in[1],  (const float*)d_in[2],  (const float*)d_in[3],
        (const float*)d_in[4],  (const float*)d_in[5],  (const float*)d_in[6],
        (const float*)d_in[7],  (const float*)d_in[8],  (const float*)d_in[9],
        (const float*)d_in[10], (const float*)d_in[11], (const float*)d_in[12],
        (const float*)d_in[13], (const float*)d_in[14]);

    cudaFuncSetAttribute(cnn_kernel, cudaFuncAttributeMaxDynamicSharedMemorySize, SMEM_BYTES);
    cnn_kernel<<<NSM, 256, SMEM_BYTES>>>(in, (float*)d_out);
}

// round 4
// speedup vs baseline: 1.0068x; 1.0068x over previous
#include <cuda_runtime.h>
#include <cstdint>

#define EPS_BN 1e-5f
typedef unsigned long long u64;

// ---------------- packed f32x2 + cp.async helpers ----------------
__device__ __forceinline__ u64 pack2(float a, float b) {
    return ((u64)__float_as_uint(b) << 32) | (u64)__float_as_uint(a);
}
__device__ __forceinline__ void ffma2(u64& a, u64 x, u64 w) {
    asm("fma.rn.f32x2 %0, %1, %2, %0;" : "+l"(a) : "l"(x), "l"(w));
}
__device__ __forceinline__ u64 add2(u64 a, u64 b) {
    u64 r;
    asm("add.rn.f32x2 %0, %1, %2;" : "=l"(r) : "l"(a), "l"(b));
    return r;
}
__device__ __forceinline__ float hsum2(u64 a) {
    unsigned lo, hi;
    asm("mov.b64 {%0,%1}, %2;" : "=r"(lo), "=r"(hi) : "l"(a));
    return __uint_as_float(lo) + __uint_as_float(hi);
}
__device__ __forceinline__ void cp16(void* dst, const void* src) {
    unsigned d = (unsigned)__cvta_generic_to_shared(dst);
    asm volatile("cp.async.cg.shared.global [%0], [%1], 16;" :: "r"(d), "l"(src) : "memory");
}
__device__ __forceinline__ void cp_commit() {
    asm volatile("cp.async.commit_group;" ::: "memory");
}
__device__ __forceinline__ void cp_wait3() {
    asm volatile("cp.async.wait_group 3;" ::: "memory");
}

static constexpr int NSM = 148;

// SMEM map (bytes)
static constexpr int OFF_W    = 0;        // 6144 u64 folded weights   (49152)
static constexpr int OFF_X    = 49152;    // 5 x 24576 x-stage buffers (122880)
static constexpr int OFF_PART = 172032;   // 4224 u64 reduce scratch   (33792)
static constexpr int OFF_R1   = 205824;   // 512 f
static constexpr int OFF_RES  = 207872;   // 32 f
static constexpr int OFF_T1   = 208000;   // 16 f
static constexpr int OFF_W2   = 208064;   // 64 f
static constexpr int OFF_T2   = 208320;   // 4 f
static constexpr int OFF_W3   = 208336;   // 4 f
static constexpr int OFF_B3   = 208352;   // 1 f
static constexpr int SMEM_BYTES = 208384;

// Prefetch one quarter (192 k = 12 gmem rows) of strip s into buffer xb.
// gmem float4 (row rgg, cols 4c..4c+3) IS x cell (kq = rg*4+dxq, patch p): transpose free.
__device__ __forceinline__ void prefetch_q(float4* xb, const float* gin, int q,
                                           int th, int tl) {
#pragma unroll
    for (int it = 0; it < 6; it++) {
        int rg  = 2 * it + th;           // 0..11 local row
        int rgg = q * 12 + rg;           // 0..47 global (ch,dy) row
        const float* src = gin + (size_t)(rgg >> 4) * 262144 + (rgg & 15) * 512 + tl * 4;
        int slot = it * 256 + (4 * th + (tl & 3)) * 32 + (tl >> 2);
        cp16(xb + slot, src);
    }
}

__global__ void __launch_bounds__(256, 1)
cnn_kernel(const float* __restrict__ in, float* __restrict__ out,
           const float* __restrict__ w1, const float* __restrict__ b1,
           const float* __restrict__ g1, const float* __restrict__ be1,
           const float* __restrict__ m1, const float* __restrict__ v1,
           const float* __restrict__ w2, const float* __restrict__ b2,
           const float* __restrict__ g2, const float* __restrict__ be2,
           const float* __restrict__ m2, const float* __restrict__ v2,
           const float* __restrict__ w3, const float* __restrict__ b3) {
    extern __shared__ char smem[];
    u64*    wsm   = (u64*)(smem + OFF_W);
    u64*    part  = (u64*)(smem + OFF_PART);
    float*  r1    = (float*)(smem + OFF_R1);
    float*  res   = (float*)(smem + OFF_RES);
    float*  sh_t1 = (float*)(smem + OFF_T1);
    float*  sh_w2 = (float*)(smem + OFF_W2);
    float*  sh_t2 = (float*)(smem + OFF_T2);
    float*  sh_w3 = (float*)(smem + OFF_W3);
    float*  sh_b3 = (float*)(smem + OFF_B3);

    const int t  = threadIdx.x;
    const int th = t >> 7;        // 0..1
    const int tl = t & 127;       // 0..127
    const int pg = t & 7;
    const int cg = (t >> 3) & 1;
    const int kc = t >> 4;        // 0..15

    const int s0 = blockIdx.x;
    int ns = 0;
    for (int s = s0; s < 1024; s += NSM) ns++;
    const int nstages = ns * 4;

    // ---- prologue: issue stages 0..2 immediately (DRAM starts now) ----
#pragma unroll
    for (int g0 = 0; g0 < 3; g0++) {
        if (g0 < nstages) {
            int s = s0;  // g0>>2 == 0
            const float* gin = in + (size_t)(s >> 5) * 786432 + (size_t)(s & 31) * 8192;
            prefetch_q((float4*)(smem + OFF_X + g0 * 24576), gin, g0, th, tl);
        }
        cp_commit();
    }

    // ---- fold BN1 into conv weights, build small params (hides prefetch latency) ----
#pragma unroll 4
    for (int j = 0; j < 24; j++) {
        int idx = j * 256 + t;            // 0..6143
        int c  = idx & 15;
        int kp = (idx >> 4) & 1;
        int kq = idx >> 5;
        int k  = kq * 4 + kp * 2;
        float s1 = __ldg(g1 + c) * rsqrtf(__ldg(v1 + c) + EPS_BN);
        float a  = __ldg(w1 + c * 768 + k)     * s1;
        float bb = __ldg(w1 + c * 768 + k + 1) * s1;
        wsm[kq * 32 + kp * 16 + c] = pack2(a, bb);
    }
    if (t < 16) {
        float s1 = __ldg(g1 + t) * rsqrtf(__ldg(v1 + t) + EPS_BN);
        sh_t1[t] = __ldg(b1 + t) * s1 + __ldg(be1 + t) - __ldg(m1 + t) * s1;
    }
    if (t < 64) {
        int o = t >> 4;
        float s2 = __ldg(g2 + o) * rsqrtf(__ldg(v2 + o) + EPS_BN);
        sh_w2[t] = __ldg(w2 + t) * s2;
    }
    if (t < 4) {
        float s2 = __ldg(g2 + t) * rsqrtf(__ldg(v2 + t) + EPS_BN);
        sh_t2[t] = __ldg(b2 + t) * s2 + __ldg(be2 + t) - __ldg(m2 + t) * s2;
        sh_w3[t] = __ldg(w3 + t);
    }
    if (t == 0) sh_b3[0] = __ldg(b3);
    __syncthreads();   // weights visible

    u64 acc[8][4];
#pragma unroll
    for (int c = 0; c < 8; c++)
#pragma unroll
        for (int pi = 0; pi < 4; pi++) acc[c][pi] = 0ull;

    int buf_g  = 0;  // g % 5
    int buf_gi = 3;  // (g+3) % 5

    for (int g = 0; g < nstages; g++) {
        // ---- issue stage g+3 (races only with compute g-1 in a DIFFERENT buffer) ----
        int gi = g + 3;
        if (gi < nstages) {
            int s = s0 + (gi >> 2) * NSM;
            const float* gin = in + (size_t)(s >> 5) * 786432 + (size_t)(s & 31) * 8192;
            prefetch_q((float4*)(smem + OFF_X + buf_gi * 24576), gin, gi & 3, th, tl);
        }
        cp_commit();

        cp_wait3();        // stage g's group retired (FIFO, g+4 committed, <=3 pending)
        __syncthreads();   // data visible to all + all threads done with stage g-1

        // ---- compute quarter: 3 kq-iterations, 64 ffma2 each ----
        const int q = g & 3;
        const ulonglong2* xb = (const ulonglong2*)(smem + OFF_X + buf_g * 24576);
#pragma unroll
        for (int i = 0; i < 3; i++) {
            int kql = i * 16 + kc;        // 0..47
            int kqg = q * 48 + kql;       // 0..191
            ulonglong2 xv[4];
#pragma unroll
            for (int pi = 0; pi < 4; pi++)
                xv[pi] = xb[kql * 32 + pi * 8 + pg];

            const ulonglong2* w0p = (const ulonglong2*)(wsm + kqg * 32 + cg * 8);
            const ulonglong2* w1p = w0p + 8;
            u64 wa[8], wb[8];
#pragma unroll
            for (int gg = 0; gg < 4; gg++) {
                ulonglong2 a = w0p[gg]; wa[2 * gg] = a.x; wa[2 * gg + 1] = a.y;
                ulonglong2 b = w1p[gg]; wb[2 * gg] = b.x; wb[2 * gg + 1] = b.y;
            }
#pragma unroll
            for (int c = 0; c < 8; c++)
#pragma unroll
                for (int pi = 0; pi < 4; pi++) {
                    ffma2(acc[c][pi], xv[pi].x, wa[c]);
                    ffma2(acc[c][pi], xv[pi].y, wb[c]);
                }
        }

        if (++buf_g  == 5) buf_g  = 0;
        if (++buf_gi == 5) buf_gi = 0;

        // ---- strip complete: reduce + epilogue + store (cp.async keeps streaming) ----
        if (q == 3) {
            const int s = s0 + (g >> 2) * NSM;

            // fold kc parity in-warp (lane bit 4)
#pragma unroll
            for (int c = 0; c < 8; c++)
#pragma unroll
                for (int pi = 0; pi < 4; pi++) {
                    u64 o = __shfl_xor_sync(0xffffffffu, acc[c][pi], 16);
                    acc[c][pi] = add2(acc[c][pi], o);
                }
            if (!(t & 16)) {
                int w = t >> 5;
#pragma unroll
                for (int c = 0; c < 8; c++)
#pragma unroll
                    for (int pi = 0; pi < 4; pi++)
                        part[(w * 16 + cg * 8 + c) * 33 + pi * 8 + pg] = acc[c][pi];
            }
            __syncthreads();

            // sum 8 warp-partials per (patch, channel), BN bias + ReLU
#pragma unroll
            for (int jj = 0; jj < 2; jj++) {
                int o = t * 2 + jj;
                int chn = o & 15, p = o >> 4;
                u64 sm_ = part[chn * 33 + p];
#pragma unroll
                for (int w = 1; w < 8; w++) sm_ = add2(sm_, part[(w * 16 + chn) * 33 + p]);
                float v = hsum2(sm_) + sh_t1[chn];
                r1[p * 16 + chn] = fmaxf(v, 0.0f);
            }
            __syncthreads();

            // 16->4->1 funnel
            if (t < 32) {
                float z0 = sh_t2[0], z1 = sh_t2[1], z2 = sh_t2[2], z3 = sh_t2[3];
#pragma unroll
                for (int c = 0; c < 16; c++) {
                    float r = r1[t * 16 + c];
                    z0 = fmaf(r, sh_w2[c],      z0);
                    z1 = fmaf(r, sh_w2[16 + c], z1);
                    z2 = fmaf(r, sh_w2[32 + c], z2);
                    z3 = fmaf(r, sh_w2[48 + c], z3);
                }
                float o = sh_b3[0];
                o = fmaf(fmaxf(z0, 0.f), sh_w3[0], o);
                o = fmaf(fmaxf(z1, 0.f), sh_w3[1], o);
                o = fmaf(fmaxf(z2, 0.f), sh_w3[2], o);
                o = fmaf(fmaxf(z3, 0.f), sh_w3[3], o);
                res[t] = o;
            }
            __syncthreads();

            // 16x upsample store: 16 rows x 512 cols, streaming float4
            float* gout = out + (size_t)(s >> 5) * 262144 + (size_t)(s & 31) * 8192;
#pragma unroll
            for (int it = 0; it < 8; it++) {
                int idx  = it * 256 + t;
                int row  = idx >> 7;
                int col4 = idx & 127;
                float v = res[col4 >> 2];
                __stcs((float4*)(gout + row * 512 + col4 * 4), make_float4(v, v, v, v));
            }

#pragma unroll
            for (int c = 0; c < 8; c++)
#pragma unroll
                for (int pi = 0; pi < 4; pi++) acc[c][pi] = 0ull;
        }
    }
}

extern "C" void kernel_launch(void* const* d_in, const int* in_sizes, int n_in,
                              void* d_out, int out_size) {
    (void)in_sizes; (void)n_in; (void)out_size;
    cudaFuncSetAttribute(cnn_kernel, cudaFuncAttributeMaxDynamicSharedMemorySize, SMEM_BYTES);
    cnn_kernel<<<NSM, 256, SMEM_BYTES>>>(
        (const float*)d_in[0], (float*)d_out,
        (const float*)d_in[1],  (const float*)d_in[2],  (const float*)d_in[3],
        (const float*)d_in[4],  (const float*)d_in[5],  (const float*)d_in[6],
        (const float*)d_in[7],  (const float*)d_in[8],  (const float*)d_in[9],
        (const float*)d_in[10], (const float*)d_in[11], (const float*)d_in[12],
        (const float*)d_in[13], (const float*)d_in[14]);
}

// round 5
// speedup vs baseline: 1.1981x; 1.1901x over previous
#include <cuda_runtime.h>
#include <cstdint>

#define EPS_BN 1e-5f
typedef unsigned long long u64;

static constexpr int NSM = 148;

// ---------------- smem map (bytes) ----------------
static constexpr int OFF_W    = 0;        // 192 kq * 36 u64 = 55296
static constexpr int OFF_X    = 55296;    // 5 * 24576 stage buffers = 122880
static constexpr int OFF_PART = 178176;   // 64 * 33 u64 = 16896
static constexpr int OFF_R1   = 195072;   // 512 f
static constexpr int OFF_RES  = 197120;   // 32 f
static constexpr int OFF_ROW  = 197248;   // 512 f (output row)
static constexpr int OFF_MBAR = 199296;   // 5 * 8
static constexpr int OFF_T1   = 199360;
static constexpr int OFF_W2   = 199424;
static constexpr int OFF_T2   = 199680;
static constexpr int OFF_W3   = 199696;
static constexpr int OFF_B3   = 199712;
static constexpr int SMEM_BYTES = 199744;

// ---------------- helpers ----------------
__device__ __forceinline__ u64 pack2(float a, float b) {
    return ((u64)__float_as_uint(b) << 32) | (u64)__float_as_uint(a);
}
__device__ __forceinline__ void ffma2(u64& a, u64 x, u64 w) {
    asm("fma.rn.f32x2 %0, %1, %2, %0;" : "+l"(a) : "l"(x), "l"(w));
}
__device__ __forceinline__ u64 add2(u64 a, u64 b) {
    u64 r;
    asm("add.rn.f32x2 %0, %1, %2;" : "=l"(r) : "l"(a), "l"(b));
    return r;
}
__device__ __forceinline__ float hsum2(u64 a) {
    unsigned lo, hi;
    asm("mov.b64 {%0,%1}, %2;" : "=r"(lo), "=r"(hi) : "l"(a));
    return __uint_as_float(lo) + __uint_as_float(hi);
}
__device__ __forceinline__ void mbar_init(unsigned mb, unsigned cnt) {
    asm volatile("mbarrier.init.shared.b64 [%0], %1;" :: "r"(mb), "r"(cnt) : "memory");
}
__device__ __forceinline__ void mbar_wait(unsigned mb, unsigned phase) {
    asm volatile(
        "{\n\t.reg .pred P;\n"
        "W%=:\n\t"
        "mbarrier.try_wait.parity.shared.b64 P, [%0], %1;\n\t"
        "@P bra D%=;\n\t"
        "bra W%=;\n"
        "D%=:\n\t}"
        :: "r"(mb), "r"(phase) : "memory");
}
// Issue one 24KB stage: expect_tx + 12 bulk row copies (2KB each).
__device__ __forceinline__ void issue_stage(unsigned xs, const float* gin, int q, unsigned mb) {
    asm volatile("mbarrier.arrive.expect_tx.shared.b64 _, [%0], %1;"
                 :: "r"(mb), "r"(24576u) : "memory");
#pragma unroll
    for (int r = 0; r < 12; r++) {
        int rgg = q * 12 + r;
        const float* src = gin + (size_t)(rgg >> 4) * 262144 + (rgg & 15) * 512;
        asm volatile(
            "cp.async.bulk.shared::cluster.global.mbarrier::complete_tx::bytes [%0], [%1], %2, [%3];"
            :: "r"(xs + r * 2048), "l"(src), "r"(2048u), "r"(mb) : "memory");
    }
}
__device__ __forceinline__ void bulk_s2g(void* gdst, unsigned ssrc, unsigned bytes) {
    asm volatile("cp.async.bulk.global.shared::cta.bulk_group [%0], [%1], %2;"
                 :: "l"(gdst), "r"(ssrc), "r"(bytes) : "memory");
}

__global__ void __launch_bounds__(256, 1)
cnn_kernel(const float* __restrict__ in, float* __restrict__ out,
           const float* __restrict__ w1, const float* __restrict__ b1,
           const float* __restrict__ g1, const float* __restrict__ be1,
           const float* __restrict__ m1, const float* __restrict__ v1,
           const float* __restrict__ w2, const float* __restrict__ b2,
           const float* __restrict__ g2, const float* __restrict__ be2,
           const float* __restrict__ m2, const float* __restrict__ v2,
           const float* __restrict__ w3, const float* __restrict__ b3) {
    extern __shared__ char smem[];
    const unsigned sbase = (unsigned)__cvta_generic_to_shared(smem);
    u64*   wsm   = (u64*)(smem + OFF_W);
    u64*   part  = (u64*)(smem + OFF_PART);
    float* r1    = (float*)(smem + OFF_R1);
    float* res   = (float*)(smem + OFF_RES);
    float* rowb  = (float*)(smem + OFF_ROW);
    float* sh_t1 = (float*)(smem + OFF_T1);
    float* sh_w2 = (float*)(smem + OFF_W2);
    float* sh_t2 = (float*)(smem + OFF_T2);
    float* sh_w3 = (float*)(smem + OFF_W3);
    float* sh_b3 = (float*)(smem + OFF_B3);

    const int t    = threadIdx.x;
    const int lane = t & 31;
    const int warp = t >> 5;
    const int dxq  = lane & 3;          // dx quad (k within lane -> conflict-free LDS)
    const int p0   = (lane >> 2) & 1;   // patch bit 0
    const int pg4  = (lane >> 3) & 3;   // patch bits 1-2
    const int rgc  = warp & 3;          // row split across warps
    const int cg   = warp >> 2;         // channel group (8 ch each)
    const int pbase = pg4 * 2 + p0;     // patch = pi*8 + pbase
    const int xoff = pbase * 64 + dxq * 16;

    const int s0 = blockIdx.x;
    const int ns = (1024 - s0 + NSM - 1) / NSM;
    const int nstages = ns * 4;

    if (t == 0) {
#pragma unroll
        for (int i = 0; i < 5; i++) mbar_init(sbase + OFF_MBAR + i * 8, 1);
    }
    __syncthreads();

    // prologue: issue stages 0..2 of strip s0 (DRAM starts now)
    if (t == 0) {
        const float* gin = in + (size_t)(s0 >> 5) * 786432 + (size_t)(s0 & 31) * 8192;
#pragma unroll
        for (int g0 = 0; g0 < 3; g0++)
            issue_stage(sbase + OFF_X + g0 * 24576, gin, g0, sbase + OFF_MBAR + g0 * 8);
    }

    // ---- fold BN1 into conv1 weights (36 u64/kq stride = bank stagger) ----
#pragma unroll
    for (int j = 0; j < 12; j++) {
        int idx = j * 256 + t;          // 0..3071
        int c = idx & 15, kq = idx >> 4;
        float s1 = __ldg(g1 + c) * rsqrtf(__ldg(v1 + c) + EPS_BN);
        float4 w = *(const float4*)(w1 + c * 768 + kq * 4);
        wsm[kq * 36 + c]      = pack2(w.x * s1, w.y * s1);
        wsm[kq * 36 + 16 + c] = pack2(w.z * s1, w.w * s1);
    }
    if (t < 16) {
        float s1 = __ldg(g1 + t) * rsqrtf(__ldg(v1 + t) + EPS_BN);
        sh_t1[t] = __ldg(b1 + t) * s1 + __ldg(be1 + t) - __ldg(m1 + t) * s1;
    }
    if (t < 64) {
        int o = t >> 4;
        float s2 = __ldg(g2 + o) * rsqrtf(__ldg(v2 + o) + EPS_BN);
        sh_w2[t] = __ldg(w2 + t) * s2;
    }
    if (t < 4) {
        float s2 = __ldg(g2 + t) * rsqrtf(__ldg(v2 + t) + EPS_BN);
        sh_t2[t] = __ldg(b2 + t) * s2 + __ldg(be2 + t) - __ldg(m2 + t) * s2;
        sh_w3[t] = __ldg(w3 + t);
    }
    if (t == 0) sh_b3[0] = __ldg(b3);
    __syncthreads();

    u64 acc[8][4];
#pragma unroll
    for (int c = 0; c < 8; c++)
#pragma unroll
        for (int pi = 0; pi < 4; pi++) acc[c][pi] = 0ull;

    int buf_g = 0, buf_i = 3;
    unsigned phase = 0;

    for (int g = 0; g < nstages; g++) {
        // issue stage g+3 into buf (g+3)%5 (safe: readers lag at most to g-1)
        if (t == 0 && g + 3 < nstages) {
            int gi = g + 3;
            int s = s0 + (gi >> 2) * NSM;
            const float* gin = in + (size_t)(s >> 5) * 786432 + (size_t)(s & 31) * 8192;
            issue_stage(sbase + OFF_X + buf_i * 24576, gin, gi & 3,
                        sbase + OFF_MBAR + buf_i * 8);
        }

        mbar_wait(sbase + OFF_MBAR + buf_g * 8, phase);
        __syncthreads();

        const int q = g & 3;
        const char* xb = smem + OFF_X + buf_g * 24576;

#pragma unroll
        for (int i = 0; i < 3; i++) {
            const int rg = i * 4 + rgc;
            const char* xp = xb + rg * 2048 + xoff;
            ulonglong2 xv[4];
#pragma unroll
            for (int pi = 0; pi < 4; pi++)
                xv[pi] = *(const ulonglong2*)(xp + pi * 512);

            const int kqg = q * 48 + rg * 4 + dxq;
            const ulonglong2* wp = (const ulonglong2*)(wsm + kqg * 36 + cg * 8);
            u64 wa[8], wb[8];
#pragma unroll
            for (int j = 0; j < 4; j++) {
                ulonglong2 a = wp[j];     wa[2 * j] = a.x; wa[2 * j + 1] = a.y;
                ulonglong2 b = wp[j + 8]; wb[2 * j] = b.x; wb[2 * j + 1] = b.y;
            }
#pragma unroll
            for (int c = 0; c < 8; c++)
#pragma unroll
                for (int pi = 0; pi < 4; pi++) {
                    ffma2(acc[c][pi], xv[pi].x, wa[c]);
                    ffma2(acc[c][pi], xv[pi].y, wb[c]);
                }
        }

        if (++buf_g == 5) { buf_g = 0; phase ^= 1; }
        if (++buf_i == 5) buf_i = 0;

        // ---- strip complete: reduce + epilogue + bulk store ----
        if (q == 3) {
            const int s = s0 + (g >> 2) * NSM;

            // reduce dx-quad (lane bits 0-1)
#pragma unroll
            for (int c = 0; c < 8; c++)
#pragma unroll
                for (int pi = 0; pi < 4; pi++) {
                    acc[c][pi] = add2(acc[c][pi], __shfl_xor_sync(0xffffffffu, acc[c][pi], 1));
                    acc[c][pi] = add2(acc[c][pi], __shfl_xor_sync(0xffffffffu, acc[c][pi], 2));
                }
            if (dxq == 0) {
#pragma unroll
                for (int c = 0; c < 8; c++)
#pragma unroll
                    for (int pi = 0; pi < 4; pi++)
                        part[(rgc * 16 + cg * 8 + c) * 33 + pi * 8 + pbase] = acc[c][pi];
            }
            __syncthreads();

            // sum 4 rgc partials per (patch, channel), BN bias + ReLU
#pragma unroll
            for (int jj = 0; jj < 2; jj++) {
                int o = t * 2 + jj;
                int chn = o & 15, p = o >> 4;
                u64 sm_ = add2(add2(part[chn * 33 + p],        part[(16 + chn) * 33 + p]),
                               add2(part[(32 + chn) * 33 + p], part[(48 + chn) * 33 + p]));
                r1[p * 16 + chn] = fmaxf(hsum2(sm_) + sh_t1[chn], 0.0f);
            }
            __syncthreads();

            // 16->4->1 funnel
            if (t < 32) {
                float rv[16];
                const float4* rp = (const float4*)(r1 + t * 16);
#pragma unroll
                for (int j = 0; j < 4; j++) ((float4*)rv)[j] = rp[j];
                float z0 = sh_t2[0], z1 = sh_t2[1], z2 = sh_t2[2], z3 = sh_t2[3];
#pragma unroll
                for (int c = 0; c < 16; c++) {
                    z0 = fmaf(rv[c], sh_w2[c],      z0);
                    z1 = fmaf(rv[c], sh_w2[16 + c], z1);
                    z2 = fmaf(rv[c], sh_w2[32 + c], z2);
                    z3 = fmaf(rv[c], sh_w2[48 + c], z3);
                }
                float o = sh_b3[0];
                o = fmaf(fmaxf(z0, 0.f), sh_w3[0], o);
                o = fmaf(fmaxf(z1, 0.f), sh_w3[1], o);
                o = fmaf(fmaxf(z2, 0.f), sh_w3[2], o);
                o = fmaf(fmaxf(z3, 0.f), sh_w3[3], o);
                res[t] = o;
            }
            __syncthreads();

            // previous strip's bulk stores must be done reading rowb
            if (t == 0)
                asm volatile("cp.async.bulk.wait_group.read 0;" ::: "memory");
            __syncthreads();

            if (t < 128) {
                float v = res[t >> 2];
                ((float4*)rowb)[t] = make_float4(v, v, v, v);
            }
            asm volatile("fence.proxy.async.shared::cta;" ::: "memory");
            __syncthreads();

            if (t == 0) {
                float* gout = out + (size_t)(s >> 5) * 262144 + (size_t)(s & 31) * 8192;
#pragma unroll
                for (int row = 0; row < 16; row++)
                    bulk_s2g(gout + row * 512, sbase + OFF_ROW, 2048u);
                asm volatile("cp.async.bulk.commit_group;" ::: "memory");
            }

#pragma unroll
            for (int c = 0; c < 8; c++)
#pragma unroll
                for (int pi = 0; pi < 4; pi++) acc[c][pi] = 0ull;
        }
    }

    if (t == 0)
        asm volatile("cp.async.bulk.wait_group 0;" ::: "memory");
}

extern "C" void kernel_launch(void* const* d_in, const int* in_sizes, int n_in,
                              void* d_out, int out_size) {
    (void)in_sizes; (void)n_in; (void)out_size;
    cudaFuncSetAttribute(cnn_kernel, cudaFuncAttributeMaxDynamicSharedMemorySize, SMEM_BYTES);
    cnn_kernel<<<NSM, 256, SMEM_BYTES>>>(
        (const float*)d_in[0], (float*)d_out,
        (const float*)d_in[1],  (const float*)d_in[2],  (const float*)d_in[3],
        (const float*)d_in[4],  (const float*)d_in[5],  (const float*)d_in[6],
        (const float*)d_in[7],  (const float*)d_in[8],  (const float*)d_in[9],
        (const float*)d_in[10], (const float*)d_in[11], (const float*)d_in[12],
        (const float*)d_in[13], (const float*)d_in[14]);
}

// round 6
// speedup vs baseline: 1.2468x; 1.0406x over previous
#include <cuda_runtime.h>
#include <cstdint>

#define EPS_BN 1e-5f
typedef unsigned long long u64;

static constexpr int NSM     = 148;
static constexpr int NBUF    = 5;
static constexpr int STAGE_B = 12288;   // 6 rows x 2048 B

// ---------------- smem map (bytes) ----------------
static constexpr int OFF_W    = 0;        // 192 kq * 36 u64 = 55296
static constexpr int OFF_X    = 55296;    // 2 halves * 5 * 12288 = 122880
static constexpr int OFF_PART = 178176;   // 2 * 8192
static constexpr int OFF_R1   = 194560;   // 2 * 2048
static constexpr int OFF_RES  = 198656;   // 2 * 128
static constexpr int OFF_ROW  = 198912;   // 2 * 2048
static constexpr int OFF_MBAR = 203008;   // 10 * 8
static constexpr int OFF_T1   = 203088;
static constexpr int OFF_W2   = 203152;
static constexpr int OFF_T2   = 203408;
static constexpr int OFF_W3   = 203424;
static constexpr int OFF_B3   = 203440;
static constexpr int SMEM_BYTES = 203456;

// ---------------- helpers ----------------
__device__ __forceinline__ u64 pack2(float a, float b) {
    return ((u64)__float_as_uint(b) << 32) | (u64)__float_as_uint(a);
}
__device__ __forceinline__ void ffma2(u64& a, u64 x, u64 w) {
    asm("fma.rn.f32x2 %0, %1, %2, %0;" : "+l"(a) : "l"(x), "l"(w));
}
__device__ __forceinline__ u64 add2(u64 a, u64 b) {
    u64 r;
    asm("add.rn.f32x2 %0, %1, %2;" : "=l"(r) : "l"(a), "l"(b));
    return r;
}
__device__ __forceinline__ float hsum2(u64 a) {
    unsigned lo, hi;
    asm("mov.b64 {%0,%1}, %2;" : "=r"(lo), "=r"(hi) : "l"(a));
    return __uint_as_float(lo) + __uint_as_float(hi);
}
__device__ __forceinline__ void mbar_init(unsigned mb, unsigned cnt) {
    asm volatile("mbarrier.init.shared.b64 [%0], %1;" :: "r"(mb), "r"(cnt) : "memory");
}
// Sleeping wait (suspend-hint try_wait) — no hard spin through MIO.
__device__ __forceinline__ void mbar_wait(unsigned mb, unsigned phase) {
    asm volatile(
        "{\n\t.reg .pred P;\n"
        "W%=:\n\t"
        "mbarrier.try_wait.parity.shared.b64 P, [%0], %1, 0x989680;\n\t"
        "@P bra D%=;\n\t"
        "bra W%=;\n"
        "D%=:\n\t}"
        :: "r"(mb), "r"(phase) : "memory");
}
__device__ __forceinline__ void barh(int id) {
    asm volatile("bar.sync %0, 128;" :: "r"(id) : "memory");
}
// Issue one 12KB stage: expect_tx + 6 bulk row copies (2KB each).
__device__ __forceinline__ void issue_stage(unsigned xs, const float* gin, int q, unsigned mb) {
    asm volatile("mbarrier.arrive.expect_tx.shared.b64 _, [%0], %1;"
                 :: "r"(mb), "r"(12288u) : "memory");
#pragma unroll
    for (int r = 0; r < 6; r++) {
        int rgg = q * 6 + r;   // global (ch,dy) row 0..47
        const float* src = gin + (size_t)(rgg >> 4) * 262144 + (rgg & 15) * 512;
        asm volatile(
            "cp.async.bulk.shared::cluster.global.mbarrier::complete_tx::bytes [%0], [%1], %2, [%3];"
            :: "r"(xs + r * 2048), "l"(src), "r"(2048u), "r"(mb) : "memory");
    }
}
__device__ __forceinline__ void bulk_s2g(void* gdst, unsigned ssrc, unsigned bytes) {
    asm volatile("cp.async.bulk.global.shared::cta.bulk_group [%0], [%1], %2;"
                 :: "l"(gdst), "r"(ssrc), "r"(bytes) : "memory");
}

__global__ void __launch_bounds__(256, 1)
cnn_kernel(const float* __restrict__ in, float* __restrict__ out,
           const float* __restrict__ w1, const float* __restrict__ b1,
           const float* __restrict__ g1, const float* __restrict__ be1,
           const float* __restrict__ m1, const float* __restrict__ v1,
           const float* __restrict__ w2, const float* __restrict__ b2,
           const float* __restrict__ g2, const float* __restrict__ be2,
           const float* __restrict__ m2, const float* __restrict__ v2,
           const float* __restrict__ w3, const float* __restrict__ b3) {
    extern __shared__ char smem[];
    const unsigned sbase = (unsigned)__cvta_generic_to_shared(smem);

    const int t     = threadIdx.x;
    const int h     = t >> 7;          // half id 0/1 (independent pipeline)
    const int tl    = t & 127;
    const int wl    = tl >> 5;         // warp within half 0..3
    const int lane  = t & 31;
    const int rgc   = wl & 1;          // row split (2 warps)
    const int cg    = wl >> 1;         // channel group (8 ch)
    const int dxq   = lane & 3;        // dx quad
    const int pbase = lane >> 2;       // patch low bits 0..7
    const int xoff  = pbase * 64 + dxq * 16;
    const int barid = 1 + h;

    u64*   wsm   = (u64*)(smem + OFF_W);
    char*  xhb   = smem + OFF_X + h * (NBUF * STAGE_B);
    u64*   part  = (u64*)(smem + OFF_PART + h * 8192);
    float* r1    = (float*)(smem + OFF_R1 + h * 2048);
    float* res   = (float*)(smem + OFF_RES + h * 128);
    float* rowb  = (float*)(smem + OFF_ROW + h * 2048);
    float* sh_t1 = (float*)(smem + OFF_T1);
    float* sh_w2 = (float*)(smem + OFF_W2);
    float* sh_t2 = (float*)(smem + OFF_T2);
    float* sh_w3 = (float*)(smem + OFF_W3);
    float* sh_b3 = (float*)(smem + OFF_B3);
    const unsigned mb0 = sbase + OFF_MBAR + h * NBUF * 8;
    const unsigned xs0 = sbase + OFF_X + h * (NBUF * STAGE_B);

    const int s0 = blockIdx.x;
    // strips for this half: s0 + (h + 2j)*NSM
    int nsh = 0;
    for (int s = s0 + h * NSM; s < 1024; s += 2 * NSM) nsh++;
    const int nstages = nsh * 8;

    if (t == 0) {
#pragma unroll
        for (int i = 0; i < 2 * NBUF; i++) mbar_init(sbase + OFF_MBAR + i * 8, 1);
    }
    __syncthreads();

    // prologue: each half issues its stages 0..2 (DRAM starts immediately)
    if (tl == 0) {
#pragma unroll
        for (int g0 = 0; g0 < 3; g0++) {
            if (g0 < nstages) {
                int s = s0 + h * NSM;   // g0>>3 == 0
                const float* gin = in + (size_t)(s >> 5) * 786432 + (size_t)(s & 31) * 8192;
                issue_stage(xs0 + g0 * STAGE_B, gin, g0, mb0 + g0 * 8);
            }
        }
    }

    // ---- fold BN1 into conv1 weights (CTA-wide, hides prefetch latency) ----
#pragma unroll
    for (int j = 0; j < 12; j++) {
        int idx = j * 256 + t;          // 0..3071
        int c = idx & 15, kq = idx >> 4;
        float s1 = __ldg(g1 + c) * rsqrtf(__ldg(v1 + c) + EPS_BN);
        float4 w = *(const float4*)(w1 + c * 768 + kq * 4);
        wsm[kq * 36 + c]      = pack2(w.x * s1, w.y * s1);
        wsm[kq * 36 + 16 + c] = pack2(w.z * s1, w.w * s1);
    }
    if (t < 16) {
        float s1 = __ldg(g1 + t) * rsqrtf(__ldg(v1 + t) + EPS_BN);
        sh_t1[t] = __ldg(b1 + t) * s1 + __ldg(be1 + t) - __ldg(m1 + t) * s1;
    }
    if (t < 64) {
        int o = t >> 4;
        float s2 = __ldg(g2 + o) * rsqrtf(__ldg(v2 + o) + EPS_BN);
        sh_w2[t] = __ldg(w2 + t) * s2;
    }
    if (t < 4) {
        float s2 = __ldg(g2 + t) * rsqrtf(__ldg(v2 + t) + EPS_BN);
        sh_t2[t] = __ldg(b2 + t) * s2 + __ldg(be2 + t) - __ldg(m2 + t) * s2;
        sh_w3[t] = __ldg(w3 + t);
    }
    if (t == 0) sh_b3[0] = __ldg(b3);
    __syncthreads();   // LAST CTA-wide barrier; halves now fully independent

    u64 acc[8][4];
#pragma unroll
    for (int c = 0; c < 8; c++)
#pragma unroll
        for (int pi = 0; pi < 4; pi++) acc[c][pi] = 0ull;

    int buf_g = 0, buf_i = 3;
    unsigned phase = 0;

    for (int g = 0; g < nstages; g++) {
        // issue stage g+3 into buf (g+3)%5 (readers lag <=1 stage: safe by ring distance)
        if (tl == 0 && g + 3 < nstages) {
            int gi = g + 3;
            int s = s0 + (h + 2 * (gi >> 3)) * NSM;
            const float* gin = in + (size_t)(s >> 5) * 786432 + (size_t)(s & 31) * 8192;
            issue_stage(xs0 + buf_i * STAGE_B, gin, gi & 7, mb0 + buf_i * 8);
        }

        mbar_wait(mb0 + buf_g * 8, phase);
        barh(barid);   // bounds warp skew to <1 stage (buffer-reuse safety)

        const int q = g & 7;
        const char* xb = xhb + buf_g * STAGE_B;

#pragma unroll
        for (int i = 0; i < 3; i++) {
            const int rgl = i * 2 + rgc;           // 0..5 local row
            const char* xp = xb + rgl * 2048 + xoff;
            ulonglong2 xv[4];
#pragma unroll
            for (int pi = 0; pi < 4; pi++)
                xv[pi] = *(const ulonglong2*)(xp + pi * 512);

            const int kqg = (q * 6 + rgl) * 4 + dxq;     // 0..191
            const ulonglong2* wp = (const ulonglong2*)(wsm + kqg * 36 + cg * 8);
            u64 wa[8], wb[8];
#pragma unroll
            for (int j = 0; j < 4; j++) {
                ulonglong2 a = wp[j];     wa[2 * j] = a.x; wa[2 * j + 1] = a.y;
                ulonglong2 b = wp[j + 8]; wb[2 * j] = b.x; wb[2 * j + 1] = b.y;
            }
#pragma unroll
            for (int c = 0; c < 8; c++)
#pragma unroll
                for (int pi = 0; pi < 4; pi++) {
                    ffma2(acc[c][pi], xv[pi].x, wa[c]);
                    ffma2(acc[c][pi], xv[pi].y, wb[c]);
                }
        }

        if (++buf_g == NBUF) { buf_g = 0; phase ^= 1; }
        if (++buf_i == NBUF) buf_i = 0;

        // ---- strip complete: half-scoped reduce + epilogue + bulk store ----
        if (q == 7) {
            const int s = s0 + (h + 2 * (g >> 3)) * NSM;

            // reduce dx-quad (lane bits 0-1)
#pragma unroll
            for (int c = 0; c < 8; c++)
#pragma unroll
                for (int pi = 0; pi < 4; pi++) {
                    acc[c][pi] = add2(acc[c][pi], __shfl_xor_sync(0xffffffffu, acc[c][pi], 1));
                    acc[c][pi] = add2(acc[c][pi], __shfl_xor_sync(0xffffffffu, acc[c][pi], 2));
                }
            if (dxq == 0) {
#pragma unroll
                for (int c = 0; c < 8; c++)
#pragma unroll
                    for (int pi = 0; pi < 4; pi++)
                        part[rgc * 512 + (cg * 8 + c) * 32 + pi * 8 + pbase] = acc[c][pi];
            }
            barh(barid);

            // sum 2 rgc partials per (patch, channel), BN bias + ReLU
            {
                int o0 = tl * 4;
                int chn = o0 >> 5;
                ulonglong2 a0 = *(const ulonglong2*)(part + o0);
                ulonglong2 a1 = *(const ulonglong2*)(part + o0 + 2);
                ulonglong2 b0 = *(const ulonglong2*)(part + 512 + o0);
                ulonglong2 b1 = *(const ulonglong2*)(part + 512 + o0 + 2);
                u64 s_[4] = {add2(a0.x, b0.x), add2(a0.y, b0.y),
                             add2(a1.x, b1.x), add2(a1.y, b1.y)};
#pragma unroll
                for (int j = 0; j < 4; j++) {
                    int p = (o0 + j) & 31;
                    r1[p * 16 + chn] = fmaxf(hsum2(s_[j]) + sh_t1[chn], 0.0f);
                }
            }
            barh(barid);

            // 16->4->1 funnel (one warp of the half)
            if (tl < 32) {
                float rv[16];
                const float4* rp = (const float4*)(r1 + tl * 16);
#pragma unroll
                for (int j = 0; j < 4; j++) ((float4*)rv)[j] = rp[j];
                float z0 = sh_t2[0], z1 = sh_t2[1], z2 = sh_t2[2], z3 = sh_t2[3];
#pragma unroll
                for (int c = 0; c < 16; c++) {
                    z0 = fmaf(rv[c], sh_w2[c],      z0);
                    z1 = fmaf(rv[c], sh_w2[16 + c], z1);
                    z2 = fmaf(rv[c], sh_w2[32 + c], z2);
                    z3 = fmaf(rv[c], sh_w2[48 + c], z3);
                }
                float o = sh_b3[0];
                o = fmaf(fmaxf(z0, 0.f), sh_w3[0], o);
                o = fmaf(fmaxf(z1, 0.f), sh_w3[1], o);
                o = fmaf(fmaxf(z2, 0.f), sh_w3[2], o);
                o = fmaf(fmaxf(z3, 0.f), sh_w3[3], o);
                res[tl] = o;
            }
            barh(barid);

            // prior strip's bulk stores must finish READING rowb before overwrite
            if (tl == 0)
                asm volatile("cp.async.bulk.wait_group.read 0;" ::: "memory");
            barh(barid);

            {
                float v = res[tl >> 2];
                ((float4*)rowb)[tl] = make_float4(v, v, v, v);
            }
            asm volatile("fence.proxy.async.shared::cta;" ::: "memory");
            barh(barid);

            if (tl == 0) {
                float* gout = out + (size_t)(s >> 5) * 262144 + (size_t)(s & 31) * 8192;
                unsigned rsrc = sbase + OFF_ROW + h * 2048;
#pragma unroll
                for (int row = 0; row < 16; row++)
                    bulk_s2g(gout + row * 512, rsrc, 2048u);
                asm volatile("cp.async.bulk.commit_group;" ::: "memory");
            }

#pragma unroll
            for (int c = 0; c < 8; c++)
#pragma unroll
                for (int pi = 0; pi < 4; pi++) acc[c][pi] = 0ull;
        }
    }

    if (tl == 0)
        asm volatile("cp.async.bulk.wait_group 0;" ::: "memory");
}

extern "C" void kernel_launch(void* const* d_in, const int* in_sizes, int n_in,
                              void* d_out, int out_size) {
    (void)in_sizes; (void)n_in; (void)out_size;
    cudaFuncSetAttribute(cnn_kernel, cudaFuncAttributeMaxDynamicSharedMemorySize, SMEM_BYTES);
    cnn_kernel<<<NSM, 256, SMEM_BYTES>>>(
        (const float*)d_in[0], (float*)d_out,
        (const float*)d_in[1],  (const float*)d_in[2],  (const float*)d_in[3],
        (const float*)d_in[4],  (const float*)d_in[5],  (const float*)d_in[6],
        (const float*)d_in[7],  (const float*)d_in[8],  (const float*)d_in[9],
        (const float*)d_in[10], (const float*)d_in[11], (const float*)d_in[12],
        (const float*)d_in[13], (const float*)d_in[14]);
}

// round 8
// speedup vs baseline: 1.3013x; 1.0437x over previous
#include <cuda_runtime.h>
#include <cstdint>

#define EPS_BN 1e-5f
typedef unsigned long long u64;

static constexpr int NSM     = 148;
static constexpr int NBUF    = 5;
static constexpr int STAGE_B = 12288;   // 6 rows x 2048 B

// ---------------- smem map (bytes) ----------------
static constexpr int OFF_W    = 0;        // 192 kq * 36 u64 = 55296
static constexpr int OFF_X    = 55296;    // 2 halves * 5 * 12288 = 122880
static constexpr int OFF_PART = 178176;   // 2 * 8192
static constexpr int OFF_R1   = 194560;   // 2 * 2048
static constexpr int OFF_RES  = 198656;   // 2 * 128
static constexpr int OFF_ROW  = 198912;   // 2 * 2048
static constexpr int OFF_MBAR = 203008;   // 10 * 8
static constexpr int OFF_T1   = 203088;
static constexpr int OFF_W2   = 203152;
static constexpr int OFF_T2   = 203408;
static constexpr int OFF_W3   = 203424;
static constexpr int OFF_B3   = 203440;
static constexpr int SMEM_BYTES = 203456;

// ---------------- helpers ----------------
__device__ __forceinline__ u64 pack2(float a, float b) {
    return ((u64)__float_as_uint(b) << 32) | (u64)__float_as_uint(a);
}
__device__ __forceinline__ void ffma2(u64& a, u64 x, u64 w) {
    asm("fma.rn.f32x2 %0, %1, %2, %0;" : "+l"(a) : "l"(x), "l"(w));
}
__device__ __forceinline__ u64 add2(u64 a, u64 b) {
    u64 r;
    asm("add.rn.f32x2 %0, %1, %2;" : "=l"(r) : "l"(a), "l"(b));
    return r;
}
__device__ __forceinline__ float hsum2(u64 a) {
    unsigned lo, hi;
    asm("mov.b64 {%0,%1}, %2;" : "=r"(lo), "=r"(hi) : "l"(a));
    return __uint_as_float(lo) + __uint_as_float(hi);
}
__device__ __forceinline__ void mbar_init(unsigned mb, unsigned cnt) {
    asm volatile("mbarrier.init.shared.b64 [%0], %1;" :: "r"(mb), "r"(cnt) : "memory");
}
__device__ __forceinline__ void mbar_wait(unsigned mb, unsigned phase) {
    asm volatile(
        "{\n\t.reg .pred P;\n"
        "W%=:\n\t"
        "mbarrier.try_wait.parity.shared.b64 P, [%0], %1, 0x989680;\n\t"
        "@P bra D%=;\n\t"
        "bra W%=;\n"
        "D%=:\n\t}"
        :: "r"(mb), "r"(phase) : "memory");
}
__device__ __forceinline__ void barh(int id) {
    asm volatile("bar.sync %0, 128;" :: "r"(id) : "memory");
}
__device__ __forceinline__ void issue_stage(unsigned xs, const float* gin, int q, unsigned mb) {
    asm volatile("mbarrier.arrive.expect_tx.shared.b64 _, [%0], %1;"
                 :: "r"(mb), "r"(12288u) : "memory");
#pragma unroll
    for (int r = 0; r < 6; r++) {
        int rgg = q * 6 + r;
        const float* src = gin + (size_t)(rgg >> 4) * 262144 + (rgg & 15) * 512;
        asm volatile(
            "cp.async.bulk.shared::cluster.global.mbarrier::complete_tx::bytes [%0], [%1], %2, [%3];"
            :: "r"(xs + r * 2048), "l"(src), "r"(2048u), "r"(mb) : "memory");
    }
}
__device__ __forceinline__ void bulk_s2g(void* gdst, unsigned ssrc, unsigned bytes) {
    asm volatile("cp.async.bulk.global.shared::cta.bulk_group [%0], [%1], %2;"
                 :: "l"(gdst), "r"(ssrc), "r"(bytes) : "memory");
}

__global__ void __launch_bounds__(256, 1)
cnn_kernel(const float* __restrict__ in, float* __restrict__ out,
           const float* __restrict__ w1, const float* __restrict__ b1,
           const float* __restrict__ g1, const float* __restrict__ be1,
           const float* __restrict__ m1, const float* __restrict__ v1,
           const float* __restrict__ w2, const float* __restrict__ b2,
           const float* __restrict__ g2, const float* __restrict__ be2,
           const float* __restrict__ m2, const float* __restrict__ v2,
           const float* __restrict__ w3, const float* __restrict__ b3) {
    extern __shared__ char smem[];
    const unsigned sbase = (unsigned)__cvta_generic_to_shared(smem);

    const int t     = threadIdx.x;
    const int h     = t >> 7;          // half id: independent pipeline
    const int tl    = t & 127;
    const int wl    = tl >> 5;
    const int lane  = t & 31;
    const int rgc   = wl & 1;          // row split (2 warps)
    const int cg    = wl >> 1;         // channel group (8 ch)
    const int dxq   = lane & 3;
    const int pbase = lane >> 2;
    const int xoff  = pbase * 64 + dxq * 16;
    const int barid = 1 + h;

    u64*   wsm   = (u64*)(smem + OFF_W);
    char*  xhb   = smem + OFF_X + h * (NBUF * STAGE_B);
    u64*   part  = (u64*)(smem + OFF_PART + h * 8192);
    float* r1    = (float*)(smem + OFF_R1 + h * 2048);
    float* res   = (float*)(smem + OFF_RES + h * 128);
    float* rowb  = (float*)(smem + OFF_ROW + h * 2048);
    float* sh_t1 = (float*)(smem + OFF_T1);
    float* sh_w2 = (float*)(smem + OFF_W2);
    float* sh_t2 = (float*)(smem + OFF_T2);
    float* sh_w3 = (float*)(smem + OFF_W3);
    float* sh_b3 = (float*)(smem + OFF_B3);
    const unsigned mb0 = sbase + OFF_MBAR + h * NBUF * 8;
    const unsigned xs0 = sbase + OFF_X + h * (NBUF * STAGE_B);

    const int s0 = blockIdx.x;
    int nsh = 0;
    for (int s = s0 + h * NSM; s < 1024; s += 2 * NSM) nsh++;
    const int nstages = nsh * 8;

    if (t == 0) {
#pragma unroll
        for (int i = 0; i < 2 * NBUF; i++) mbar_init(sbase + OFF_MBAR + i * 8, 1);
    }
    __syncthreads();

    if (tl == 0) {
#pragma unroll
        for (int g0 = 0; g0 < 3; g0++) {
            if (g0 < nstages) {
                int s = s0 + h * NSM;
                const float* gin = in + (size_t)(s >> 5) * 786432 + (size_t)(s & 31) * 8192;
                issue_stage(xs0 + g0 * STAGE_B, gin, g0, mb0 + g0 * 8);
            }
        }
    }

    // ---- fold BN1 into conv1 weights (hides prefetch latency) ----
#pragma unroll
    for (int j = 0; j < 12; j++) {
        int idx = j * 256 + t;
        int c = idx & 15, kq = idx >> 4;
        float s1 = __ldg(g1 + c) * rsqrtf(__ldg(v1 + c) + EPS_BN);
        float4 w = *(const float4*)(w1 + c * 768 + kq * 4);
        wsm[kq * 36 + c]      = pack2(w.x * s1, w.y * s1);
        wsm[kq * 36 + 16 + c] = pack2(w.z * s1, w.w * s1);
    }
    if (t < 16) {
        float s1 = __ldg(g1 + t) * rsqrtf(__ldg(v1 + t) + EPS_BN);
        sh_t1[t] = __ldg(b1 + t) * s1 + __ldg(be1 + t) - __ldg(m1 + t) * s1;
    }
    if (t < 64) {
        int o = t >> 4;
        float s2 = __ldg(g2 + o) * rsqrtf(__ldg(v2 + o) + EPS_BN);
        sh_w2[t] = __ldg(w2 + t) * s2;
    }
    if (t < 4) {
        float s2 = __ldg(g2 + t) * rsqrtf(__ldg(v2 + t) + EPS_BN);
        sh_t2[t] = __ldg(b2 + t) * s2 + __ldg(be2 + t) - __ldg(m2 + t) * s2;
        sh_w3[t] = __ldg(w3 + t);
    }
    if (t == 0) sh_b3[0] = __ldg(b3);
    __syncthreads();   // last CTA-wide barrier

    u64 acc[8][4];
#pragma unroll
    for (int c = 0; c < 8; c++)
#pragma unroll
        for (int pi = 0; pi < 4; pi++) acc[c][pi] = 0ull;

    int buf_g = 0, buf_i = 3;
    unsigned phase = 0;

    for (int g = 0; g < nstages; g++) {
        if (tl == 0 && g + 3 < nstages) {
            int gi = g + 3;
            int s = s0 + (h + 2 * (gi >> 3)) * NSM;
            const float* gin = in + (size_t)(s >> 5) * 786432 + (size_t)(s & 31) * 8192;
            issue_stage(xs0 + buf_i * STAGE_B, gin, gi & 7, mb0 + buf_i * 8);
        }

        mbar_wait(mb0 + buf_g * 8, phase);

        const int q = g & 7;
        const char* xb = xhb + buf_g * STAGE_B;

        // register double-buffered inner loop (3 iters, 2 reg sets).
        // Plain lambdas (no annotation) — implicitly device inside kernel body.
        ulonglong2 xvA[4], xvB[4];
        u64 waA[8], wbA[8], waB[8], wbB[8];

        auto load_set = [&](int i, ulonglong2* xv, u64* wa, u64* wb) {
            const int rgl = i * 2 + rgc;
            const char* xp = xb + rgl * 2048 + xoff;
#pragma unroll
            for (int pi = 0; pi < 4; pi++)
                xv[pi] = *(const ulonglong2*)(xp + pi * 512);
            const int kqg = (q * 6 + rgl) * 4 + dxq;
            const ulonglong2* wp = (const ulonglong2*)(wsm + kqg * 36 + cg * 8);
#pragma unroll
            for (int j = 0; j < 4; j++) {
                ulonglong2 a = wp[j];     wa[2 * j] = a.x; wa[2 * j + 1] = a.y;
                ulonglong2 b = wp[j + 8]; wb[2 * j] = b.x; wb[2 * j + 1] = b.y;
            }
        };
        // two RAW-separated passes: each acc touched once per pass (32-instr distance)
        auto compute_set = [&](ulonglong2* xv, u64* wa, u64* wb) {
#pragma unroll
            for (int c = 0; c < 8; c++)
#pragma unroll
                for (int pi = 0; pi < 4; pi++)
                    ffma2(acc[c][pi], xv[pi].x, wa[c]);
#pragma unroll
            for (int c = 0; c < 8; c++)
#pragma unroll
                for (int pi = 0; pi < 4; pi++)
                    ffma2(acc[c][pi], xv[pi].y, wb[c]);
        };

        load_set(0, xvA, waA, wbA);   // overlaps barrier below
        barh(barid);                  // buffer-reuse safety (prev stage readers done)
        load_set(1, xvB, waB, wbB);   // queues while computing iter 0
        compute_set(xvA, waA, wbA);
        load_set(2, xvA, waA, wbA);   // queues while computing iter 1
        compute_set(xvB, waB, wbB);
        compute_set(xvA, waA, wbA);

        if (++buf_g == NBUF) { buf_g = 0; phase ^= 1; }
        if (++buf_i == NBUF) buf_i = 0;

        // ---- strip complete: half-scoped reduce + epilogue + bulk store ----
        if (q == 7) {
            const int s = s0 + (h + 2 * (g >> 3)) * NSM;

#pragma unroll
            for (int c = 0; c < 8; c++)
#pragma unroll
                for (int pi = 0; pi < 4; pi++) {
                    acc[c][pi] = add2(acc[c][pi], __shfl_xor_sync(0xffffffffu, acc[c][pi], 1));
                    acc[c][pi] = add2(acc[c][pi], __shfl_xor_sync(0xffffffffu, acc[c][pi], 2));
                }
            if (dxq == 0) {
#pragma unroll
                for (int c = 0; c < 8; c++)
#pragma unroll
                    for (int pi = 0; pi < 4; pi++)
                        part[rgc * 512 + (cg * 8 + c) * 32 + pi * 8 + pbase] = acc[c][pi];
            }
            barh(barid);

            {
                int o0 = tl * 4;
                int chn = o0 >> 5;
                ulonglong2 a0 = *(const ulonglong2*)(part + o0);
                ulonglong2 a1 = *(const ulonglong2*)(part + o0 + 2);
                ulonglong2 b0 = *(const ulonglong2*)(part + 512 + o0);
                ulonglong2 b1 = *(const ulonglong2*)(part + 512 + o0 + 2);
                u64 s_[4] = {add2(a0.x, b0.x), add2(a0.y, b0.y),
                             add2(a1.x, b1.x), add2(a1.y, b1.y)};
#pragma unroll
                for (int j = 0; j < 4; j++) {
                    int p = (o0 + j) & 31;
                    r1[p * 16 + chn] = fmaxf(hsum2(s_[j]) + sh_t1[chn], 0.0f);
                }
            }
            barh(barid);

            if (tl < 32) {
                float rv[16];
                const float4* rp = (const float4*)(r1 + tl * 16);
#pragma unroll
                for (int j = 0; j < 4; j++) ((float4*)rv)[j] = rp[j];
                float z0 = sh_t2[0], z1 = sh_t2[1], z2 = sh_t2[2], z3 = sh_t2[3];
#pragma unroll
                for (int c = 0; c < 16; c++) {
                    z0 = fmaf(rv[c], sh_w2[c],      z0);
                    z1 = fmaf(rv[c], sh_w2[16 + c], z1);
                    z2 = fmaf(rv[c], sh_w2[32 + c], z2);
                    z3 = fmaf(rv[c], sh_w2[48 + c], z3);
                }
                float o = sh_b3[0];
                o = fmaf(fmaxf(z0, 0.f), sh_w3[0], o);
                o = fmaf(fmaxf(z1, 0.f), sh_w3[1], o);
                o = fmaf(fmaxf(z2, 0.f), sh_w3[2], o);
                o = fmaf(fmaxf(z3, 0.f), sh_w3[3], o);
                res[tl] = o;
            }
            barh(barid);

            if (tl == 0)
                asm volatile("cp.async.bulk.wait_group.read 0;" ::: "memory");
            barh(barid);

            {
                float v = res[tl >> 2];
                ((float4*)rowb)[tl] = make_float4(v, v, v, v);
            }
            asm volatile("fence.proxy.async.shared::cta;" ::: "memory");
            barh(barid);

            if (tl == 0) {
                float* gout = out + (size_t)(s >> 5) * 262144 + (size_t)(s & 31) * 8192;
                unsigned rsrc = sbase + OFF_ROW + h * 2048;
#pragma unroll
                for (int row = 0; row < 16; row++)
                    bulk_s2g(gout + row * 512, rsrc, 2048u);
                asm volatile("cp.async.bulk.commit_group;" ::: "memory");
            }

#pragma unroll
            for (int c = 0; c < 8; c++)
#pragma unroll
                for (int pi = 0; pi < 4; pi++) acc[c][pi] = 0ull;
        }
    }

    if (tl == 0)
        asm volatile("cp.async.bulk.wait_group 0;" ::: "memory");
}

extern "C" void kernel_launch(void* const* d_in, const int* in_sizes, int n_in,
                              void* d_out, int out_size) {
    (void)in_sizes; (void)n_in; (void)out_size;
    cudaFuncSetAttribute(cnn_kernel, cudaFuncAttributeMaxDynamicSharedMemorySize, SMEM_BYTES);
    cnn_kernel<<<NSM, 256, SMEM_BYTES>>>(
        (const float*)d_in[0], (float*)d_out,
        (const float*)d_in[1],  (const float*)d_in[2],  (const float*)d_in[3],
        (const float*)d_in[4],  (const float*)d_in[5],  (const float*)d_in[6],
        (const float*)d_in[7],  (const float*)d_in[8],  (const float*)d_in[9],
        (const float*)d_in[10], (const float*)d_in[11], (const float*)d_in[12],
        (const float*)d_in[13], (const float*)d_in[14]);
}